// round 12
// baseline (speedup 1.0000x reference)
#include <cuda_runtime.h>
#include <cstdint>

// Problem constants
#define BQ   4
#define NP   16384
#define PQ   2048
#define CF   64
#define NS   32
#define TILE 2048
#define CAP  768
#define QPW  4     // queries per warp

// Scratch: final (masked) neighbor indices per (b,p,s)
__device__ int g_idx[BQ * PQ * NS];

__device__ __forceinline__ unsigned long long warpMinULL(unsigned long long v) {
#pragma unroll
    for (int off = 16; off; off >>= 1) {
        unsigned long long o = __shfl_xor_sync(0xffffffffu, v, off);
        if (o < v) v = o;
    }
    return v;
}

__device__ __forceinline__ unsigned fkey(float f) {
    unsigned b = __float_as_uint(f);
    return (b & 0x80000000u) ? ~b : (b | 0x80000000u);
}

// q2 chain (queries, scalar left-assoc reduce):
//   q2 = rn( rn(x^2 + y^2) + z^2 )
__device__ __forceinline__ float sq_L(float x, float y, float z) {
    return __fadd_rn(__fadd_rn(__fmul_rn(x, x), __fmul_rn(y, y)),
                     __fmul_rn(z, z));
}
// p2 chain (points, SIMD split-half horizontal reduce of (x2,y2,z2,0)):
//   p2 = rn( rn(x^2 + z^2) + y^2 )
__device__ __forceinline__ float sq_H(float x, float y, float z) {
    return __fadd_rn(__fadd_rn(__fmul_rn(x, x), __fmul_rn(z, z)),
                     __fmul_rn(y, y));
}

// cross: ascending-k fma chain (chain A)
// d2 = rn( rn(q2 + p2) - 2*cross )   (2*cross exact)
__device__ __forceinline__ float d2_ref(float qx, float qy, float qz, float q2,
                                        float x, float y, float z) {
    float p2 = sq_H(x, y, z);
    float cr = __fmaf_rn(qz, z, __fmaf_rn(qy, y, __fmul_rn(qx, x)));
    return __fadd_rn(__fadd_rn(q2, p2), __fmul_rn(-2.0f, cr));
}

// ---------------------------------------------------------------------------
// Kernel 1: KNN with radius filtering.
// Block: 256 threads = 8 warps, each warp owns 4 queries -> 32 queries/block.
// Shared: float4 tile (-2x,-2y,-2z,p2_H) + 32 candidate buffers + counters.
// Scaling coords by -2 (exact power of two) commutes with every rounding
// step of the fma chain, so the chain below yields -2*cross bit-exactly.
// ---------------------------------------------------------------------------
__global__ void __launch_bounds__(256, 1)
knn_kernel(const float* __restrict__ xyz, const float* __restrict__ nxyz) {
    extern __shared__ char smem[];
    float4* tile = (float4*)smem;
    unsigned long long* buf = (unsigned long long*)(smem + TILE * 16);
    int* cnt = (int*)(smem + TILE * 16 + 32 * CAP * 8);

    // keep iff d2 <= 0.25 + 2^-25 (equivalent to fl(sqrt(d2)) <= 0.5)
    const float KEEP = __uint_as_float(0x3E800001u);

    const int tid = threadIdx.x;
    const int lane = tid & 31;
    const int warp = tid >> 5;
    const int qbase = blockIdx.x * 32 + warp * QPW;
    const int b = qbase / PQ;
    const float* __restrict__ Xb = xyz + (size_t)b * NP * 3;

    float qx[QPW], qy[QPW], qz[QPW], q2[QPW];
#pragma unroll
    for (int i = 0; i < QPW; i++) {
        int gq = qbase + i;
        qx[i] = nxyz[gq * 3 + 0];
        qy[i] = nxyz[gq * 3 + 1];
        qz[i] = nxyz[gq * 3 + 2];
        q2[i] = sq_L(qx[i], qy[i], qz[i]);     // queries: left-assoc
    }
    if (tid < 32) cnt[tid] = 0;

    // ---- filtered scan over all N points, tiled through shared memory ----
    for (int t0 = 0; t0 < NP; t0 += TILE) {
        if (t0) __syncthreads();           // previous tile fully consumed
        for (int j = tid; j < TILE; j += 256) {
            int gi = t0 + j;
            float x = Xb[gi * 3 + 0];
            float y = Xb[gi * 3 + 1];
            float z = Xb[gi * 3 + 2];
            tile[j] = make_float4(-2.0f * x, -2.0f * y, -2.0f * z,
                                  sq_H(x, y, z));  // points: split-half
        }
        __syncthreads();

        for (int j = lane; j < TILE; j += 32) {
            float4 pt = tile[j];
#pragma unroll
            for (int qi = 0; qi < QPW; qi++) {
                // m2cross = -2 * cross, bitwise, ascending-k fma chain (A)
                float m2cross = __fmaf_rn(qz[qi], pt.z,
                                 __fmaf_rn(qy[qi], pt.y,
                                  __fmul_rn(qx[qi], pt.x)));
                float s = __fadd_rn(q2[qi], pt.w);   // rn(q2 + p2)
                float d2 = __fadd_rn(s, m2cross);    // rn(s - 2*cross)
                if (d2 <= KEEP) {
                    unsigned long long e =
                        ((unsigned long long)fkey(d2) << 32) | (unsigned)(t0 + j);
                    int slot = warp * QPW + qi;
                    int pos = atomicAdd(&cnt[slot], 1);
                    if (pos < CAP) buf[(size_t)slot * CAP + pos] = e;
                }
            }
        }
    }
    __syncwarp();

    // ---- per-query selection: 32 smallest (d2, idx) lexicographic ----
#pragma unroll 1
    for (int qi = 0; qi < QPW; qi++) {
        const int slot = warp * QPW + qi;
        const int gq = qbase + qi;
        const int c = cnt[slot];
        unsigned long long mine = 0;

        if (c > CAP) {
            // overflow (>CAP within radius): exact 32 rounds over global xyz.
            unsigned long long prev = 0;
            for (int r = 0; r < NS; r++) {
                unsigned long long best = ~0ull;
                for (int i = lane; i < NP; i += 32) {
                    float d2 = d2_ref(qx[qi], qy[qi], qz[qi], q2[qi],
                                      Xb[i * 3 + 0], Xb[i * 3 + 1], Xb[i * 3 + 2]);
                    unsigned long long e =
                        ((unsigned long long)fkey(d2) << 32) | (unsigned)i;
                    if (e > prev && e < best) best = e;
                }
                unsigned long long w = warpMinULL(best);
                prev = w;
                if (lane == r) mine = w;
            }
        } else if (c == 0) {
            // no point within radius: every sample = overall nearest neighbor
            unsigned long long best = ~0ull;
            for (int i = lane; i < NP; i += 32) {
                float d2 = d2_ref(qx[qi], qy[qi], qz[qi], q2[qi],
                                  Xb[i * 3 + 0], Xb[i * 3 + 1], Xb[i * 3 + 2]);
                unsigned long long e =
                    ((unsigned long long)fkey(d2) << 32) | (unsigned)i;
                if (e < best) best = e;
            }
            mine = warpMinULL(best);       // same for all lanes
        } else {
            const int rounds = c < NS ? c : NS;
            unsigned long long prev = 0, first = 0;
            for (int r = 0; r < rounds; r++) {
                unsigned long long best = ~0ull;
                for (int i = lane; i < c; i += 32) {
                    unsigned long long e = buf[(size_t)slot * CAP + i];
                    if (e > prev && e < best) best = e;
                }
                unsigned long long w = warpMinULL(best);
                prev = w;
                if (r == 0) first = w;
                if (lane == r) mine = w;
            }
            if (lane >= rounds) mine = first;   // masked samples -> idx[0]
        }
        g_idx[gq * NS + lane] = (int)(mine & 0xffffffffu);
    }
}

// ---------------------------------------------------------------------------
// Kernel 2: gather. One block per (b,p). 256 threads: s = tid&31, cg = tid>>5.
// outA: new_features (B,67,P,32); outB: grouped_xyz (B,3,P,32).
// ---------------------------------------------------------------------------
__global__ void __launch_bounds__(256)
gather_kernel(const float* __restrict__ xyz, const float* __restrict__ nxyz,
              const float* __restrict__ feat,
              float* __restrict__ outA, float* __restrict__ outB, int writeB) {
    const int bp = blockIdx.x;             // 0..8191
    const int b = bp >> 11;
    const int p = bp & 2047;
    const int tid = threadIdx.x;
    const int s = tid & 31;
    const int cg = tid >> 5;

    __shared__ int sidx[NS];
    __shared__ float sg[3][NS];

    if (tid < NS) {
        int i = g_idx[bp * NS + tid];
        sidx[tid] = i;
        const float* pt = xyz + ((size_t)b * NP + i) * 3;
        const float* q = nxyz + (size_t)bp * 3;
        sg[0][tid] = pt[0] - q[0];
        sg[1][tid] = pt[1] - q[1];
        sg[2][tid] = pt[2] - q[2];
    }
    __syncthreads();

    const int i = sidx[s];
    const float* __restrict__ fb = feat + (size_t)b * CF * NP;

    for (int ch = cg; ch < 67; ch += 8) {
        float v = (ch < 3) ? sg[ch][s] : fb[(size_t)(ch - 3) * NP + i];
        outA[(((size_t)b * 67 + ch) * PQ + p) * NS + s] = v;
    }
    if (writeB && cg < 3) {
        outB[(((size_t)b * 3 + cg) * PQ + p) * NS + s] = sg[cg][s];
    }
}

// ---------------------------------------------------------------------------
extern "C" void kernel_launch(void* const* d_in, const int* in_sizes, int n_in,
                              void* d_out, int out_size) {
    const float* xyz  = (const float*)d_in[0];   // (B,N,3)
    const float* nxyz = (const float*)d_in[1];   // (B,NPOINT,3)
    const float* feat = (const float*)d_in[2];   // (B,C,N)
    float* out = (float*)d_out;

    const size_t segA = (size_t)BQ * 67 * PQ * NS;   // new_features
    const size_t segB = (size_t)BQ * 3 * PQ * NS;    // grouped_xyz
    const int writeB = ((size_t)out_size >= segA + segB) ? 1 : 0;

    const size_t smemB = (size_t)TILE * 16 + 32ull * CAP * 8 + 128;
    cudaFuncSetAttribute(knn_kernel, cudaFuncAttributeMaxDynamicSharedMemorySize,
                         (int)smemB);

    knn_kernel<<<(BQ * PQ) / 32, 256, smemB>>>(xyz, nxyz);
    gather_kernel<<<BQ * PQ, 256>>>(xyz, nxyz, feat, out, out + segA, writeB);
}

// round 13
// speedup vs baseline: 1.3007x; 1.3007x over previous
#include <cuda_runtime.h>
#include <cstdint>

// Problem constants
#define BQ   4
#define NP   16384
#define PQ   2048
#define CF   64
#define NS   32
#define TILE 2048
#define CAP  768
#define QPW  2     // queries per warp
#define NTHR 512   // 16 warps

// Scratch: final (masked) neighbor indices per (b,p,s)
__device__ int g_idx[BQ * PQ * NS];
// Scratch: transposed features (B, N, C)
__device__ float g_ft[BQ * NP * CF];

__device__ __forceinline__ unsigned long long warpMinULL(unsigned long long v) {
#pragma unroll
    for (int off = 16; off; off >>= 1) {
        unsigned long long o = __shfl_xor_sync(0xffffffffu, v, off);
        if (o < v) v = o;
    }
    return v;
}

__device__ __forceinline__ unsigned fkey(float f) {
    unsigned b = __float_as_uint(f);
    return (b & 0x80000000u) ? ~b : (b | 0x80000000u);
}

// ===== FROZEN reference-bitwise arithmetic (validated rel_err == 0.0) =====
// q2 chain (queries, scalar left-assoc):   rn( rn(x^2 + y^2) + z^2 )
__device__ __forceinline__ float sq_L(float x, float y, float z) {
    return __fadd_rn(__fadd_rn(__fmul_rn(x, x), __fmul_rn(y, y)),
                     __fmul_rn(z, z));
}
// p2 chain (points, SIMD split-half):      rn( rn(x^2 + z^2) + y^2 )
__device__ __forceinline__ float sq_H(float x, float y, float z) {
    return __fadd_rn(__fadd_rn(__fmul_rn(x, x), __fmul_rn(z, z)),
                     __fmul_rn(y, y));
}
// cross: ascending-k fma chain; d2 = rn( rn(q2+p2) - 2*cross )
__device__ __forceinline__ float d2_ref(float qx, float qy, float qz, float q2,
                                        float x, float y, float z) {
    float p2 = sq_H(x, y, z);
    float cr = __fmaf_rn(qz, z, __fmaf_rn(qy, y, __fmul_rn(qx, x)));
    return __fadd_rn(__fadd_rn(q2, p2), __fmul_rn(-2.0f, cr));
}
// ==========================================================================

// ---------------------------------------------------------------------------
// Kernel 1: KNN with radius filtering. 512 threads = 16 warps, QPW=2 ->
// 32 queries/block, 256 blocks. Warp-private buffers: register counter +
// ballot compaction (no atomics, no smem counters).
// Tile stores (-2x,-2y,-2z,p2_H); -2 scaling is exact and commutes with every
// rounding of the fma chain -> m2cross is -2*cross bitwise.
// ---------------------------------------------------------------------------
__global__ void __launch_bounds__(NTHR, 1)
knn_kernel(const float* __restrict__ xyz, const float* __restrict__ nxyz) {
    extern __shared__ char smem[];
    float4* tile = (float4*)smem;
    unsigned long long* buf = (unsigned long long*)(smem + TILE * 16);

    // keep iff d2 <= 0.25 + 2^-25 (== fl(sqrt(d2)) <= 0.5)
    const float KEEP = __uint_as_float(0x3E800001u);

    const int tid = threadIdx.x;
    const int lane = tid & 31;
    const int warp = tid >> 5;
    const unsigned ltmask = (1u << lane) - 1u;
    const int qbase = blockIdx.x * 32 + warp * QPW;
    const int b = qbase / PQ;
    const float* __restrict__ Xb = xyz + (size_t)b * NP * 3;

    float qx[QPW], qy[QPW], qz[QPW], q2[QPW];
    int cnt[QPW];
#pragma unroll
    for (int i = 0; i < QPW; i++) {
        int gq = qbase + i;
        qx[i] = nxyz[gq * 3 + 0];
        qy[i] = nxyz[gq * 3 + 1];
        qz[i] = nxyz[gq * 3 + 2];
        q2[i] = sq_L(qx[i], qy[i], qz[i]);     // queries: left-assoc
        cnt[i] = 0;
    }

    // ---- filtered scan over all N points, tiled through shared memory ----
    for (int t0 = 0; t0 < NP; t0 += TILE) {
        if (t0) __syncthreads();           // previous tile fully consumed
        for (int j = tid; j < TILE; j += NTHR) {
            int gi = t0 + j;
            float x = Xb[gi * 3 + 0];
            float y = Xb[gi * 3 + 1];
            float z = Xb[gi * 3 + 2];
            tile[j] = make_float4(-2.0f * x, -2.0f * y, -2.0f * z,
                                  sq_H(x, y, z));  // points: split-half
        }
        __syncthreads();

        for (int j = lane; j < TILE; j += 32) {
            float4 pt = tile[j];
#pragma unroll
            for (int qi = 0; qi < QPW; qi++) {
                // m2cross = -2 * cross, bitwise, ascending-k fma chain (A)
                float m2cross = __fmaf_rn(qz[qi], pt.z,
                                 __fmaf_rn(qy[qi], pt.y,
                                  __fmul_rn(qx[qi], pt.x)));
                float s = __fadd_rn(q2[qi], pt.w);   // rn(q2 + p2)
                float d2 = __fadd_rn(s, m2cross);    // rn(s - 2*cross)
                bool pass = (d2 <= KEEP);
                unsigned m = __ballot_sync(0xffffffffu, pass);
                if (m) {
                    int pos = cnt[qi] + __popc(m & ltmask);
                    if (pass && pos < CAP)
                        buf[(size_t)(warp * QPW + qi) * CAP + pos] =
                            ((unsigned long long)fkey(d2) << 32) |
                            (unsigned)(t0 + j);
                    cnt[qi] += __popc(m);
                }
            }
        }
    }
    __syncwarp();

    // ---- per-query selection: 32 smallest (d2, idx) lexicographic ----
#pragma unroll 1
    for (int qi = 0; qi < QPW; qi++) {
        const int slot = warp * QPW + qi;
        const int gq = qbase + qi;
        const int c = cnt[qi];              // warp-uniform
        unsigned long long mine = 0;

        if (c > CAP) {
            // overflow (>CAP within radius): exact 32 rounds over global xyz.
            unsigned long long prev = 0;
            for (int r = 0; r < NS; r++) {
                unsigned long long best = ~0ull;
                for (int i = lane; i < NP; i += 32) {
                    float d2 = d2_ref(qx[qi], qy[qi], qz[qi], q2[qi],
                                      Xb[i * 3 + 0], Xb[i * 3 + 1], Xb[i * 3 + 2]);
                    unsigned long long e =
                        ((unsigned long long)fkey(d2) << 32) | (unsigned)i;
                    if (e > prev && e < best) best = e;
                }
                unsigned long long w = warpMinULL(best);
                prev = w;
                if (lane == r) mine = w;
            }
        } else if (c == 0) {
            // no point within radius: every sample = overall nearest neighbor
            unsigned long long best = ~0ull;
            for (int i = lane; i < NP; i += 32) {
                float d2 = d2_ref(qx[qi], qy[qi], qz[qi], q2[qi],
                                  Xb[i * 3 + 0], Xb[i * 3 + 1], Xb[i * 3 + 2]);
                unsigned long long e =
                    ((unsigned long long)fkey(d2) << 32) | (unsigned)i;
                if (e < best) best = e;
            }
            mine = warpMinULL(best);       // same for all lanes
        } else {
            const int rounds = c < NS ? c : NS;
            unsigned long long prev = 0, first = 0;
            for (int r = 0; r < rounds; r++) {
                unsigned long long best = ~0ull;
                for (int i = lane; i < c; i += 32) {
                    unsigned long long e = buf[(size_t)slot * CAP + i];
                    if (e > prev && e < best) best = e;
                }
                unsigned long long w = warpMinULL(best);
                prev = w;
                if (r == 0) first = w;
                if (lane == r) mine = w;
            }
            if (lane >= rounds) mine = first;   // masked samples -> idx[0]
        }
        g_idx[gq * NS + lane] = (int)(mine & 0xffffffffu);
    }
}

// ---------------------------------------------------------------------------
// Kernel 2: feature transpose (B,C,N) -> (B,N,C). Classic 32x32 smem tile.
// grid (NP/32, 2*BQ), block (32,8).
// ---------------------------------------------------------------------------
__global__ void __launch_bounds__(256)
transpose_kernel(const float* __restrict__ feat) {
    __shared__ float t[32][33];
    const int n0 = blockIdx.x * 32;
    const int c0 = (blockIdx.y & 1) * 32;
    const int b  = blockIdx.y >> 1;
    const float* __restrict__ fb = feat + (size_t)b * CF * NP;
    for (int i = threadIdx.y; i < 32; i += 8)
        t[i][threadIdx.x] = fb[(size_t)(c0 + i) * NP + n0 + threadIdx.x];
    __syncthreads();
    float* __restrict__ ft = g_ft + (size_t)b * NP * CF;
    for (int i = threadIdx.y; i < 32; i += 8)
        ft[(size_t)(n0 + i) * CF + c0 + threadIdx.x] = t[threadIdx.x][i];
}

// ---------------------------------------------------------------------------
// Kernel 3: gather from transposed features. One block per (b,p).
// Rows staged in smem via fully-coalesced float4 loads (8 lanes cover one
// 256B row), then coalesced output writes.
// ---------------------------------------------------------------------------
__global__ void __launch_bounds__(256)
gather_kernel(const float* __restrict__ xyz, const float* __restrict__ nxyz,
              float* __restrict__ outA, float* __restrict__ outB, int writeB) {
    const int bp = blockIdx.x;             // 0..8191
    const int b = bp >> 11;
    const int p = bp & 2047;
    const int tid = threadIdx.x;
    const int s = tid & 31;
    const int cg = tid >> 5;

    __shared__ int sidx[NS];
    __shared__ float sg[3][NS];
    __shared__ float srow[NS][CF + 1];     // +1: odd stride, conflict-free

    if (tid < NS) {
        int i = g_idx[bp * NS + tid];
        sidx[tid] = i;
        const float* pt = xyz + ((size_t)b * NP + i) * 3;
        const float* q = nxyz + (size_t)bp * 3;
        sg[0][tid] = pt[0] - q[0];
        sg[1][tid] = pt[1] - q[1];
        sg[2][tid] = pt[2] - q[2];
    }
    __syncthreads();

    // stage 32 feature rows: thread t -> row r=t/8, part=t%8 (8 floats each)
    {
        int r = tid >> 3, part = tid & 7;
        const float4* src = (const float4*)(g_ft +
                            ((size_t)b * NP + sidx[r]) * CF) + part * 2;
        float4 v0 = src[0];
        float4 v1 = src[1];
        float* dst = &srow[r][part * 8];
        dst[0] = v0.x; dst[1] = v0.y; dst[2] = v0.z; dst[3] = v0.w;
        dst[4] = v1.x; dst[5] = v1.y; dst[6] = v1.z; dst[7] = v1.w;
    }
    __syncthreads();

    for (int ch = cg; ch < 67; ch += 8) {
        float v = (ch < 3) ? sg[ch][s] : srow[s][ch - 3];
        outA[(((size_t)b * 67 + ch) * PQ + p) * NS + s] = v;
    }
    if (writeB && cg < 3) {
        outB[(((size_t)b * 3 + cg) * PQ + p) * NS + s] = sg[cg][s];
    }
}

// ---------------------------------------------------------------------------
extern "C" void kernel_launch(void* const* d_in, const int* in_sizes, int n_in,
                              void* d_out, int out_size) {
    const float* xyz  = (const float*)d_in[0];   // (B,N,3)
    const float* nxyz = (const float*)d_in[1];   // (B,NPOINT,3)
    const float* feat = (const float*)d_in[2];   // (B,C,N)
    float* out = (float*)d_out;

    const size_t segA = (size_t)BQ * 67 * PQ * NS;   // new_features
    const size_t segB = (size_t)BQ * 3 * PQ * NS;    // grouped_xyz
    const int writeB = ((size_t)out_size >= segA + segB) ? 1 : 0;

    const size_t smemB = (size_t)TILE * 16 + 32ull * CAP * 8 + 128;
    cudaFuncSetAttribute(knn_kernel, cudaFuncAttributeMaxDynamicSharedMemorySize,
                         (int)smemB);

    transpose_kernel<<<dim3(NP / 32, 2 * BQ), dim3(32, 8)>>>(feat);
    knn_kernel<<<(BQ * PQ) / 32, NTHR, smemB>>>(xyz, nxyz);
    gather_kernel<<<BQ * PQ, 256>>>(xyz, nxyz, out, out + segA, writeB);
}

// round 14
// speedup vs baseline: 1.6164x; 1.2427x over previous
#include <cuda_runtime.h>
#include <cstdint>

// Problem constants
#define BQ   4
#define NP   16384
#define PQ   2048
#define CF   64
#define NS   32
#define TILE 2048
#define CAP  768
#define QPW  2     // queries per warp
#define NTHR 256   // 8 warps, 16 queries per block

// Scratch: final (masked) neighbor indices per (b,p,s)
__device__ int g_idx[BQ * PQ * NS];
// Scratch: transposed features (B, N, C)
__device__ float g_ft[BQ * NP * CF];
// Scratch: per-query candidate buffers (global; tiny traffic, L1-resident reads)
__device__ unsigned long long g_cand[(size_t)BQ * PQ * CAP];

__device__ __forceinline__ unsigned long long warpMinULL(unsigned long long v) {
#pragma unroll
    for (int off = 16; off; off >>= 1) {
        unsigned long long o = __shfl_xor_sync(0xffffffffu, v, off);
        if (o < v) v = o;
    }
    return v;
}

__device__ __forceinline__ unsigned fkey(float f) {
    unsigned b = __float_as_uint(f);
    return (b & 0x80000000u) ? ~b : (b | 0x80000000u);
}

// ===== FROZEN reference-bitwise arithmetic (validated rel_err == 0.0) =====
// q2 chain (queries, scalar left-assoc):   rn( rn(x^2 + y^2) + z^2 )
__device__ __forceinline__ float sq_L(float x, float y, float z) {
    return __fadd_rn(__fadd_rn(__fmul_rn(x, x), __fmul_rn(y, y)),
                     __fmul_rn(z, z));
}
// p2 chain (points, SIMD split-half):      rn( rn(x^2 + z^2) + y^2 )
__device__ __forceinline__ float sq_H(float x, float y, float z) {
    return __fadd_rn(__fadd_rn(__fmul_rn(x, x), __fmul_rn(z, z)),
                     __fmul_rn(y, y));
}
// cross: ascending-k fma chain; d2 = rn( rn(q2+p2) - 2*cross )
__device__ __forceinline__ float d2_ref(float qx, float qy, float qz, float q2,
                                        float x, float y, float z) {
    float p2 = sq_H(x, y, z);
    float cr = __fmaf_rn(qz, z, __fmaf_rn(qy, y, __fmul_rn(qx, x)));
    return __fadd_rn(__fadd_rn(q2, p2), __fmul_rn(-2.0f, cr));
}
// ==========================================================================

// ---------------------------------------------------------------------------
// Kernel 1: KNN with radius filtering. 256 threads = 8 warps, QPW=2 ->
// 16 queries/block, 512 blocks (single full wave at ~6 blocks/SM).
// Candidates go to global scratch (ballot-compacted, no atomics).
// Tile stores (-2x,-2y,-2z,p2_H); -2 scaling is exact and commutes with every
// rounding of the fma chain -> m2cross is -2*cross bitwise.
// ---------------------------------------------------------------------------
__global__ void __launch_bounds__(NTHR)
knn_kernel(const float* __restrict__ xyz, const float* __restrict__ nxyz) {
    __shared__ float4 tile[TILE];

    // keep iff d2 <= 0.25 + 2^-25 (== fl(sqrt(d2)) <= 0.5)
    const float KEEP = __uint_as_float(0x3E800001u);

    const int tid = threadIdx.x;
    const int lane = tid & 31;
    const int warp = tid >> 5;
    const unsigned ltmask = (1u << lane) - 1u;
    const int qbase = blockIdx.x * (NTHR / 32 * QPW) + warp * QPW;
    const int b = qbase / PQ;
    const float* __restrict__ Xb = xyz + (size_t)b * NP * 3;

    float qx[QPW], qy[QPW], qz[QPW], q2[QPW];
    int cnt[QPW];
    unsigned long long* bufq[QPW];
#pragma unroll
    for (int i = 0; i < QPW; i++) {
        int gq = qbase + i;
        qx[i] = nxyz[gq * 3 + 0];
        qy[i] = nxyz[gq * 3 + 1];
        qz[i] = nxyz[gq * 3 + 2];
        q2[i] = sq_L(qx[i], qy[i], qz[i]);     // queries: left-assoc
        cnt[i] = 0;
        bufq[i] = g_cand + (size_t)gq * CAP;
    }

    // ---- filtered scan over all N points, tiled through shared memory ----
    for (int t0 = 0; t0 < NP; t0 += TILE) {
        if (t0) __syncthreads();           // previous tile fully consumed
        for (int j = tid; j < TILE; j += NTHR) {
            int gi = t0 + j;
            float x = Xb[gi * 3 + 0];
            float y = Xb[gi * 3 + 1];
            float z = Xb[gi * 3 + 2];
            tile[j] = make_float4(-2.0f * x, -2.0f * y, -2.0f * z,
                                  sq_H(x, y, z));  // points: split-half
        }
        __syncthreads();

        for (int j = lane; j < TILE; j += 32) {
            float4 pt = tile[j];
#pragma unroll
            for (int qi = 0; qi < QPW; qi++) {
                // m2cross = -2 * cross, bitwise, ascending-k fma chain (A)
                float m2cross = __fmaf_rn(qz[qi], pt.z,
                                 __fmaf_rn(qy[qi], pt.y,
                                  __fmul_rn(qx[qi], pt.x)));
                float s = __fadd_rn(q2[qi], pt.w);   // rn(q2 + p2)
                float d2 = __fadd_rn(s, m2cross);    // rn(s - 2*cross)
                bool pass = (d2 <= KEEP);
                unsigned m = __ballot_sync(0xffffffffu, pass);
                if (m) {
                    int pos = cnt[qi] + __popc(m & ltmask);
                    if (pass && pos < CAP)
                        bufq[qi][pos] =
                            ((unsigned long long)fkey(d2) << 32) |
                            (unsigned)(t0 + j);
                    cnt[qi] += __popc(m);
                }
            }
        }
    }
    __syncwarp();

    // ---- per-query selection: 32 smallest (d2, idx) lexicographic ----
#pragma unroll 1
    for (int qi = 0; qi < QPW; qi++) {
        const int gq = qbase + qi;
        const int c = cnt[qi];              // warp-uniform
        unsigned long long mine = 0;

        if (c > CAP) {
            // overflow (>CAP within radius): exact 32 rounds over global xyz.
            unsigned long long prev = 0;
            for (int r = 0; r < NS; r++) {
                unsigned long long best = ~0ull;
                for (int i = lane; i < NP; i += 32) {
                    float d2 = d2_ref(qx[qi], qy[qi], qz[qi], q2[qi],
                                      Xb[i * 3 + 0], Xb[i * 3 + 1], Xb[i * 3 + 2]);
                    unsigned long long e =
                        ((unsigned long long)fkey(d2) << 32) | (unsigned)i;
                    if (e > prev && e < best) best = e;
                }
                unsigned long long w = warpMinULL(best);
                prev = w;
                if (lane == r) mine = w;
            }
        } else if (c == 0) {
            // no point within radius: every sample = overall nearest neighbor
            unsigned long long best = ~0ull;
            for (int i = lane; i < NP; i += 32) {
                float d2 = d2_ref(qx[qi], qy[qi], qz[qi], q2[qi],
                                  Xb[i * 3 + 0], Xb[i * 3 + 1], Xb[i * 3 + 2]);
                unsigned long long e =
                    ((unsigned long long)fkey(d2) << 32) | (unsigned)i;
                if (e < best) best = e;
            }
            mine = warpMinULL(best);       // same for all lanes
        } else {
            const unsigned long long* __restrict__ buf = bufq[qi];
            const int rounds = c < NS ? c : NS;
            unsigned long long prev = 0, first = 0;
            for (int r = 0; r < rounds; r++) {
                unsigned long long best = ~0ull;
                for (int i = lane; i < c; i += 32) {
                    unsigned long long e = buf[i];
                    if (e > prev && e < best) best = e;
                }
                unsigned long long w = warpMinULL(best);
                prev = w;
                if (r == 0) first = w;
                if (lane == r) mine = w;
            }
            if (lane >= rounds) mine = first;   // masked samples -> idx[0]
        }
        g_idx[gq * NS + lane] = (int)(mine & 0xffffffffu);
    }
}

// ---------------------------------------------------------------------------
// Kernel 2: feature transpose (B,C,N) -> (B,N,C). Classic 32x32 smem tile.
// grid (NP/32, 2*BQ), block (32,8).
// ---------------------------------------------------------------------------
__global__ void __launch_bounds__(256)
transpose_kernel(const float* __restrict__ feat) {
    __shared__ float t[32][33];
    const int n0 = blockIdx.x * 32;
    const int c0 = (blockIdx.y & 1) * 32;
    const int b  = blockIdx.y >> 1;
    const float* __restrict__ fb = feat + (size_t)b * CF * NP;
    for (int i = threadIdx.y; i < 32; i += 8)
        t[i][threadIdx.x] = fb[(size_t)(c0 + i) * NP + n0 + threadIdx.x];
    __syncthreads();
    float* __restrict__ ft = g_ft + (size_t)b * NP * CF;
    for (int i = threadIdx.y; i < 32; i += 8)
        ft[(size_t)(n0 + i) * CF + c0 + threadIdx.x] = t[threadIdx.x][i];
}

// ---------------------------------------------------------------------------
// Kernel 3: gather from transposed features. One block per (b,p).
// Rows staged in smem via fully-coalesced float4 loads, coalesced writes out.
// ---------------------------------------------------------------------------
__global__ void __launch_bounds__(256)
gather_kernel(const float* __restrict__ xyz, const float* __restrict__ nxyz,
              float* __restrict__ outA, float* __restrict__ outB, int writeB) {
    const int bp = blockIdx.x;             // 0..8191
    const int b = bp >> 11;
    const int p = bp & 2047;
    const int tid = threadIdx.x;
    const int s = tid & 31;
    const int cg = tid >> 5;

    __shared__ int sidx[NS];
    __shared__ float sg[3][NS];
    __shared__ float srow[NS][CF + 1];     // +1: odd stride, conflict-free

    if (tid < NS) {
        int i = g_idx[bp * NS + tid];
        sidx[tid] = i;
        const float* pt = xyz + ((size_t)b * NP + i) * 3;
        const float* q = nxyz + (size_t)bp * 3;
        sg[0][tid] = pt[0] - q[0];
        sg[1][tid] = pt[1] - q[1];
        sg[2][tid] = pt[2] - q[2];
    }
    __syncthreads();

    // stage 32 feature rows: thread t -> row r=t/8, part=t%8 (8 floats each)
    {
        int r = tid >> 3, part = tid & 7;
        const float4* src = (const float4*)(g_ft +
                            ((size_t)b * NP + sidx[r]) * CF) + part * 2;
        float4 v0 = src[0];
        float4 v1 = src[1];
        float* dst = &srow[r][part * 8];
        dst[0] = v0.x; dst[1] = v0.y; dst[2] = v0.z; dst[3] = v0.w;
        dst[4] = v1.x; dst[5] = v1.y; dst[6] = v1.z; dst[7] = v1.w;
    }
    __syncthreads();

    for (int ch = cg; ch < 67; ch += 8) {
        float v = (ch < 3) ? sg[ch][s] : srow[s][ch - 3];
        outA[(((size_t)b * 67 + ch) * PQ + p) * NS + s] = v;
    }
    if (writeB && cg < 3) {
        outB[(((size_t)b * 3 + cg) * PQ + p) * NS + s] = sg[cg][s];
    }
}

// ---------------------------------------------------------------------------
extern "C" void kernel_launch(void* const* d_in, const int* in_sizes, int n_in,
                              void* d_out, int out_size) {
    const float* xyz  = (const float*)d_in[0];   // (B,N,3)
    const float* nxyz = (const float*)d_in[1];   // (B,NPOINT,3)
    const float* feat = (const float*)d_in[2];   // (B,C,N)
    float* out = (float*)d_out;

    const size_t segA = (size_t)BQ * 67 * PQ * NS;   // new_features
    const size_t segB = (size_t)BQ * 3 * PQ * NS;    // grouped_xyz
    const int writeB = ((size_t)out_size >= segA + segB) ? 1 : 0;

    transpose_kernel<<<dim3(NP / 32, 2 * BQ), dim3(32, 8)>>>(feat);
    knn_kernel<<<(BQ * PQ) / (NTHR / 32 * QPW), NTHR>>>(xyz, nxyz);
    gather_kernel<<<BQ * PQ, 256>>>(xyz, nxyz, out, out + segA, writeB);
}